// round 15
// baseline (speedup 1.0000x reference)
#include <cuda_runtime.h>
#include <cuda_bf16.h>

#define KDIM  64
#define LOG2E 1.4426950408889634f
#define LN2   0.6931471805599453f
#define TH    -1000000.0f
#define FULL  0xffffffffu

typedef unsigned long long ull;

__device__ __forceinline__ float ex2f(float x){float y;asm("ex2.approx.f32 %0,%1;":"=f"(y):"f"(x));return y;}
__device__ __forceinline__ float lg2f(float x){float y;asm("lg2.approx.f32 %0,%1;":"=f"(y):"f"(x));return y;}
__device__ __forceinline__ unsigned cvt_bf2(float hi, float lo){
    unsigned r;asm("cvt.rn.satfinite.bf16x2.f32 %0,%1,%2;":"=r"(r):"f"(hi),"f"(lo));return r;}
__device__ __forceinline__ float bflo(unsigned u){ return __int_as_float(u << 16); }
__device__ __forceinline__ float bfhi(unsigned u){ return __int_as_float(u & 0xFFFF0000u); }
__device__ __forceinline__ void mma0(float&d0,float&d1,float&d2,float&d3,
                                     unsigned a0,unsigned a2,unsigned b0,unsigned b1){
    asm("mma.sync.aligned.m16n8k16.row.col.f32.bf16.bf16.f32 "
        "{%0,%1,%2,%3},{%4,%5,%6,%7},{%8,%9},{%10,%10,%10,%10};"
        :"=f"(d0),"=f"(d1),"=f"(d2),"=f"(d3)
        :"r"(a0),"r"(0u),"r"(a2),"r"(0u),"r"(b0),"r"(b1),"f"(0.0f));
}
__device__ __forceinline__ void mmaA(float&d0,float&d1,float&d2,float&d3,
                                     unsigned a0,unsigned a2,unsigned b0,unsigned b1){
    asm("mma.sync.aligned.m16n8k16.row.col.f32.bf16.bf16.f32 "
        "{%0,%1,%2,%3},{%4,%5,%6,%7},{%8,%9},{%0,%1,%2,%3};"
        :"+f"(d0),"+f"(d1),"+f"(d2),"+f"(d3)
        :"r"(a0),"r"(0u),"r"(a2),"r"(0u),"r"(b0),"r"(b1));
}

// CTA = 128 thr = 4 warps cooperating on 8 batch rows (rows = groups g of lanes).
// Warp w computes n-tiles nt = 2w, 2w+1 (cols 16w..16w+15) -> 8 HMMA/warp/step.
// Feedback: D tiles (2w, 2w+1) ARE state chunk kt = w -> exchange = 1 STS.64 +
// __syncthreads + 4 LDS.64 per lane. Masks: per-warp partial ballots in a 4-slot
// smem ring (published for step T+1 pre-bar at step T, read pre-bar at T+1).
// Per-row renorm identical to R13: d = bf16 exp-field of state 0 (group-shfl),
// exact packed-exponent subtract, C2i += d. Steps t >= N run masked (frame shift).
__global__ __launch_bounds__(128, 1) void crf_mma_kernel(
    const float* __restrict__ y_pred,   // [B, N, K]
    const float* __restrict__ trans,    // [K, K]
    const int*   __restrict__ y_true,   // [B, N]
    float*       __restrict__ out,      // [B]
    int N, int B)
{
    __shared__ ull sh_st[2][4][32];     // [buf][chunk kt][lane] state (a0|a2<<32)
    __shared__ unsigned sh_mv[4][4];    // [slot][warp] partial mask ballots

    const int lane = threadIdx.x & 31;
    const int w    = threadIdx.x >> 5;
    const int g    = lane >> 2;
    const int t4   = lane & 3;
    const int rraw = blockIdx.x * 8 + g;
    const int row  = (rraw < B) ? rraw : (B - 1);

    const float* Y  = y_pred + (size_t)row * N * KDIM;
    const int*   Tr = y_true + (size_t)row * N;

    // ---- B fragments for my 2 n-tiles: [kt][ntl], col = 16w + 8*ntl + g ----
    unsigned Bf0[4][2], Bf1[4][2];
#pragma unroll
    for (int kt = 0; kt < 4; ++kt)
#pragma unroll
        for (int ntl = 0; ntl < 2; ++ntl) {
            int c = 16 * w + 8 * ntl + g, r0 = 16 * kt + 2 * t4;
            Bf0[kt][ntl] = cvt_bf2(__expf(trans[(r0 + 1) * KDIM + c]),
                                   __expf(trans[(r0    ) * KDIM + c]));
            Bf1[kt][ntl] = cvt_bf2(__expf(trans[(r0 + 9) * KDIM + c]),
                                   __expf(trans[(r0 + 8) * KDIM + c]));
        }

    // ---- t = 0: full state computed identically in every warp ----
    float2 ee[4], eo[4];
#pragma unroll
    for (int k = 0; k < 4; ++k) {
        ee[k] = *(const float2*)(Y + 16 * k + 2 * t4);
        eo[k] = *(const float2*)(Y + 16 * k + 8 + 2 * t4);
    }
    float mn0 = fminf(fminf(ee[0].x, ee[0].y), fminf(eo[0].x, eo[0].y));
#pragma unroll
    for (int k = 1; k < 4; ++k)
        mn0 = fminf(mn0, fminf(fminf(ee[k].x, ee[k].y), fminf(eo[k].x, eo[k].y)));
    mn0 = fminf(mn0, __shfl_xor_sync(FULL, mn0, 1));
    mn0 = fminf(mn0, __shfl_xor_sync(FULL, mn0, 2));
    float fm0 = (mn0 > TH) ? 1.0f : 0.0f;

    unsigned ia0[4], ia2[4];
#pragma unroll
    for (int k = 0; k < 4; ++k) {
        ia0[k] = cvt_bf2(ex2f(ee[k].y * fm0 * LOG2E), ex2f(ee[k].x * fm0 * LOG2E));
        ia2[k] = cvt_bf2(ex2f(eo[k].y * fm0 * LOG2E), ex2f(eo[k].x * fm0 * LOG2E));
    }
    sh_st[0][w][lane] = (ull)ia0[w] | ((ull)ia2[w] << 32);
    int C2i = 0;

    int yt0 = Tr[0];
    float point = Y[yt0] * fm0;
    float tv = 0.0f, fmprev = fm0;

    // ---- emit ring (my cols only): c0 = nt 2w, c1 = nt 2w+1 ----
    const int c0 = 16 * w + 2 * t4, c1 = c0 + 8;
    float2 ring[4][2];
#pragma unroll
    for (int p = 1; p <= 4; ++p) {
        int tt = (p < N) ? p : (N - 1);
        ring[p & 3][0] = *(const float2*)(Y + (size_t)tt * KDIM + c0);
        ring[p & 3][1] = *(const float2*)(Y + (size_t)tt * KDIM + c1);
    }
    {   // vote for step 1 into slot 1
        float mn = fminf(fminf(ring[1][0].x, ring[1][0].y),
                         fminf(ring[1][1].x, ring[1][1].y));
        unsigned vb = __ballot_sync(FULL, mn > TH);
        sh_mv[1][w] = (1 < N) ? vb : 0u;
    }
    // label pipeline (all warps, identical; R13-verified indices)
    int ytA = Tr[(1 < N) ? 1 : (N - 1)];
    int ytB = Tr[(2 < N) ? 2 : (N - 1)];
    int ytC = Tr[(3 < N) ? 3 : (N - 1)];
    int ytD = Tr[(4 < N) ? 4 : (N - 1)];
    float pgc = Y[(size_t)((1 < N) ? 1 : (N - 1)) * KDIM + ytA];
    float pgn = Y[(size_t)((2 < N) ? 2 : (N - 1)) * KDIM + ytB];
    float trvc = trans[yt0 * KDIM + ytA];
    float trvn = trans[ytA * KDIM + ytB];
    __syncthreads();                       // publishes state(0) + vote slot 1

#define STEP(T, SLOT, SLOTN, BUF, PBUF)                                              \
    {                                                                                \
        float2 ev0 = ring[SLOT][0], ev1 = ring[SLOT][1];                             \
        /* vote for step T+1 from slot SLOTN */                                      \
        float mn = fminf(fminf(ring[SLOTN][0].x, ring[SLOTN][0].y),                  \
                         fminf(ring[SLOTN][1].x, ring[SLOTN][1].y));                 \
        unsigned vb = __ballot_sync(FULL, mn > TH);                                  \
        sh_mv[SLOTN][w] = ((T) + 1 < N) ? vb : 0u;                                   \
        /* refill SLOT with step T+4 */                                              \
        int tl = ((T) + 4 < N) ? ((T) + 4) : (N - 1);                                \
        ring[SLOT][0] = *(const float2*)(Y + (size_t)tl * KDIM + c0);                \
        ring[SLOT][1] = *(const float2*)(Y + (size_t)tl * KDIM + c1);                \
        /* this step's mask (published at T-1, bar T-1 in between) */                \
        unsigned Vand = sh_mv[SLOT][0] & sh_mv[SLOT][1] & sh_mv[SLOT][2] & sh_mv[SLOT][3]; \
        unsigned mcur = (((Vand >> (lane & 28)) & 0xFu) == 0xFu);                    \
        float pa0 = ex2f(ev0.x * LOG2E), pb0 = ex2f(ev0.y * LOG2E);                  \
        float pa1 = ex2f(ev1.x * LOG2E), pb1 = ex2f(ev1.y * LOG2E);                  \
        int ytL = Tr[tl];                                                            \
        float pgN = Y[(size_t)(((T) + 2 < N) ? ((T) + 2) : (N - 1)) * KDIM + ytC];   \
        float trN = trans[ytB * KDIM + ytC];                                         \
        __syncthreads();                                                             \
        /* reassemble full A state(t-1) */                                           \
        ull s0 = sh_st[PBUF][0][lane], s1 = sh_st[PBUF][1][lane];                    \
        ull s2 = sh_st[PBUF][2][lane], s3 = sh_st[PBUF][3][lane];                    \
        unsigned a00 = (unsigned)s0, a20 = (unsigned)(s0 >> 32);                     \
        unsigned a01 = (unsigned)s1, a21 = (unsigned)(s1 >> 32);                     \
        unsigned a02 = (unsigned)s2, a22 = (unsigned)(s2 >> 32);                     \
        unsigned a03 = (unsigned)s3, a23 = (unsigned)(s3 >> 32);                     \
        int d = __shfl_sync(FULL, (int)((a00 >> 7) & 0xFFu) - 127, lane & ~3);       \
        /* two independent 2-deep chains per ntl, then FADD */                       \
        float xA0,xA1,xA2,xA3, xB0,xB1,xB2,xB3;                                      \
        float yA0,yA1,yA2,yA3, yB0,yB1,yB2,yB3;                                      \
        mma0(xA0,xA1,xA2,xA3, a00,a20, Bf0[0][0], Bf1[0][0]);                        \
        mma0(yA0,yA1,yA2,yA3, a00,a20, Bf0[0][1], Bf1[0][1]);                        \
        mma0(xB0,xB1,xB2,xB3, a02,a22, Bf0[2][0], Bf1[2][0]);                        \
        mma0(yB0,yB1,yB2,yB3, a02,a22, Bf0[2][1], Bf1[2][1]);                        \
        mmaA(xA0,xA1,xA2,xA3, a01,a21, Bf0[1][0], Bf1[1][0]);                        \
        mmaA(yA0,yA1,yA2,yA3, a01,a21, Bf0[1][1], Bf1[1][1]);                        \
        mmaA(xB0,xB1,xB2,xB3, a03,a23, Bf0[3][0], Bf1[3][0]);                        \
        mmaA(yB0,yB1,yB2,yB3, a03,a23, Bf0[3][1], Bf1[3][1]);                        \
        float f0 = xA0 + xB0, f1 = xA1 + xB1;     /* nt = 2w   */                    \
        float h0 = yA0 + yB0, h1 = yA1 + yB1;     /* nt = 2w+1 */                    \
        unsigned pk0 = cvt_bf2(f1 * pb0, f0 * pa0);                                  \
        unsigned pk1 = cvt_bf2(h1 * pb1, h0 * pa1);                                  \
        unsigned oldw0 = (w == 0) ? a00 : (w == 1) ? a01 : (w == 2) ? a02 : a03;     \
        unsigned oldw1 = (w == 0) ? a20 : (w == 1) ? a21 : (w == 2) ? a22 : a23;     \
        unsigned dd2 = (unsigned)(d * 0x00800080);                                   \
        unsigned r0 = (mcur ? pk0 : oldw0) - dd2;                                    \
        unsigned r1 = (mcur ? pk1 : oldw1) - dd2;                                    \
        sh_st[BUF][w][lane] = (ull)r0 | ((ull)r1 << 32);                             \
        C2i += d;                                                                    \
        float fmc = mcur ? 1.0f : 0.0f;                                              \
        point += pgc * fmc;                                                          \
        tv += trvc * (fmprev * fmc);                                                 \
        fmprev = fmc;                                                                \
        pgc = pgn; pgn = pgN;                                                        \
        trvc = trvn; trvn = trN;                                                     \
        ytA = ytB; ytB = ytC; ytC = ytD; ytD = ytL;                                  \
    }

    // ---- main loop: t0 === 1 (mod 4); steps t >= N run masked (harmless) ----
    for (int t0 = 1; t0 < N; t0 += 4) {
        STEP(t0 + 0, 1, 2, 1, 0)
        STEP(t0 + 1, 2, 3, 0, 1)
        STEP(t0 + 2, 3, 0, 1, 0)
        STEP(t0 + 3, 0, 1, 0, 1)
    }
#undef STEP

    // ---- epilogue ----
    __syncthreads();
    {
        int t0l = ((N - 2) / 4) * 4 + 1;        // last loop base
        int bufL = (t0l + 3) & 1;               // buffer written by final step
        ull s0 = sh_st[bufL][0][lane], s1 = sh_st[bufL][1][lane];
        ull s2 = sh_st[bufL][2][lane], s3 = sh_st[bufL][3][lane];
        float se = 0.0f;
        ull ss[4] = {s0, s1, s2, s3};
#pragma unroll
        for (int k = 0; k < 4; ++k) {
            unsigned lo = (unsigned)ss[k], hi = (unsigned)(ss[k] >> 32);
            se += bflo(lo) + bfhi(lo) + bflo(hi) + bfhi(hi);
        }
        se += __shfl_xor_sync(FULL, se, 1);
        se += __shfl_xor_sync(FULL, se, 2);
        if (w == 0 && t4 == 0 && rraw < B)
            out[rraw] = LN2 * ((float)C2i + lg2f(se)) - (point + tv);
    }
}

extern "C" void kernel_launch(void* const* d_in, const int* in_sizes, int n_in,
                              void* d_out, int out_size) {
    const float* y_pred = (const float*)d_in[0];   // [B, N, K] f32
    const float* trans  = (const float*)d_in[1];   // [K, K]    f32
    const int*   y_true = (const int*)  d_in[2];   // [B, N]    i32
    float* out = (float*)d_out;                    // [B]       f32

    int B = out_size;                  // 512
    int N = in_sizes[2] / B;           // 1024
    int blocks = (B + 7) / 8;          // 64 CTAs, 8 rows each, 4 warps
    crf_mma_kernel<<<blocks, 128>>>(y_pred, trans, y_true, out, N, B);
}

// round 16
// speedup vs baseline: 2.8086x; 2.8086x over previous
#include <cuda_runtime.h>
#include <cuda_bf16.h>

#define KDIM  64
#define LOG2E 1.4426950408889634f
#define LN2   0.6931471805599453f
#define WPC   4          // warps (rows) per CTA
#define DIST  4          // emit prefetch distance (steps), power of 2
#define TH    -1000000.0f
#define FULL  0xffffffffu

__device__ __forceinline__ float ex2f(float x){float y;asm("ex2.approx.f32 %0,%1;":"=f"(y):"f"(x));return y;}
__device__ __forceinline__ float lg2f(float x){float y;asm("lg2.approx.f32 %0,%1;":"=f"(y):"f"(x));return y;}
// pack {hi,lo} f32 -> bf16x2, saturate-finite
__device__ __forceinline__ unsigned cvt_bf2(float hi, float lo){
    unsigned r;asm("cvt.rn.satfinite.bf16x2.f32 %0,%1,%2;":"=r"(r):"f"(hi),"f"(lo));return r;}
__device__ __forceinline__ float bflo(unsigned u){ return __int_as_float(u << 16); }
__device__ __forceinline__ float bfhi(unsigned u){ return __int_as_float(u & 0xFFFF0000u); }
__device__ __forceinline__ unsigned hfma2(unsigned a, unsigned b, unsigned c){
    unsigned d; asm("fma.rn.bf16x2 %0,%1,%2,%3;":"=r"(d):"r"(a),"r"(b),"r"(c)); return d;}
__device__ __forceinline__ unsigned hadd2(unsigned a, unsigned b){
    unsigned d; asm("add.rn.bf16x2 %0,%1,%2;":"=r"(d):"r"(a),"r"(b)); return d;}

// ONE WARP per batch row (R6 skeleton); lane l owns states (2l, 2l+1), state kept
// PACKED bf16x2 (lo = e_{2l}, hi = e_{2l+1}). Exp-domain recursion, no per-step
// lg2/ex2 on the chain. Dot s = e x E in bf16 HFMA2 (64 instrs = 128 MACs, true
// dual-MAC, vs 128 FFMA after f32x2 lowering on sm_100a). sh_e = 32 u32 (128 B):
// 8 LDS.128 per step. Renorm: d = bf16 exp-field of state 0 (one broadcast LDS),
// applied as exact packed-exponent subtract (d * 0x00800080); C2i += d (integer).
// Steps t >= N run masked (m=0): pure frame shift, result invariant.
__global__ __launch_bounds__(32 * WPC, 1) void crf_fwd_kernel(
    const float* __restrict__ y_pred,   // [B, N, K]
    const float* __restrict__ trans,    // [K, K]
    const int*   __restrict__ y_true,   // [B, N]
    float*       __restrict__ out,      // [B]
    int N, int B)
{
    __shared__ __align__(16) unsigned sh_e[WPC][2][32];  // [warp][buf][pair k]

    const int lane = threadIdx.x & 31;
    const int w    = threadIdx.x >> 5;
    const int row  = blockIdx.x * WPC + w;
    if (row >= B) return;

    const int sa = 2 * lane, sb = sa + 1;

    // E columns in bf16x2: Eca[k] = (lo=E[2k][sa], hi=E[2k+1][sa]); Ecb for sb.
    unsigned Eca[32], Ecb[32];
#pragma unroll
    for (int k = 0; k < 32; ++k) {
        Eca[k] = cvt_bf2(__expf(trans[(2 * k + 1) * KDIM + sa]),
                         __expf(trans[(2 * k) * KDIM + sa]));
        Ecb[k] = cvt_bf2(__expf(trans[(2 * k + 1) * KDIM + sb]),
                         __expf(trans[(2 * k) * KDIM + sb]));
    }

    const float* yrow = y_pred + (size_t)row * N * KDIM;
    const int*   trow = y_true + (size_t)row * N;

    // ---- t = 0 ----
    float2 y0 = *(const float2*)(yrow + sa);
    int yt0 = trow[0];
    unsigned m0 = __all_sync(FULL, (y0.x > TH) && (y0.y > TH));
    float fm0 = m0 ? 1.0f : 0.0f;
    unsigned e = cvt_bf2(ex2f((y0.y * fm0) * LOG2E), ex2f((y0.x * fm0) * LOG2E));
    float point = ((sa == yt0) ? y0.x * fm0 : 0.0f) + ((sb == yt0) ? y0.y * fm0 : 0.0f);
    int   C2i = 0;
    float tv = 0.0f;
    sh_e[w][0][lane] = e;
    float fmprev = fm0;

    // ---- prime pipelines (R6 discipline) ----
    float2 ring[DIST];
#pragma unroll
    for (int p = 1; p <= DIST; ++p) {
        int tt = (p < N) ? p : (N - 1);
        ring[p & (DIST - 1)] = *(const float2*)(yrow + (size_t)tt * KDIM + sa);
    }
    int yt_cur = trow[(1 < N) ? 1 : (N - 1)];
    int yt_nx  = trow[(2 < N) ? 2 : (N - 1)];
    float trv_cur = trans[yt0 * KDIM + yt_cur];
    unsigned mcur = __all_sync(FULL, (ring[1 & (DIST - 1)].x > TH) &&
                                     (ring[1 & (DIST - 1)].y > TH));
    if (1 >= N) mcur = 0u;
    float fmcur = mcur ? 1.0f : 0.0f;

#define STEP(T, RP, RPN, BUF, PBUF)                                                  \
    {                                                                                \
        float2 yv = ring[RP];                                                        \
        int tt = ((T) + DIST < N) ? ((T) + DIST) : (N - 1);                          \
        ring[RP] = *(const float2*)(yrow + (size_t)tt * KDIM + sa);                  \
        unsigned mnext = __all_sync(FULL, (ring[RPN].x > TH) && (ring[RPN].y > TH)); \
        mnext = ((T) + 1 < N) ? mnext : 0u;                                          \
        int tn = ((T) + 2 < N) ? ((T) + 2) : (N - 1);                                \
        int yt_nx2 = trow[tn];                                                       \
        float trv_next = trans[yt_cur * KDIM + yt_nx];                               \
        float fl2 = fmcur * LOG2E;                                                   \
        float pa = ex2f(yv.x * fl2);   /* MUFU pre-sync: latency hidden */           \
        float pb = ex2f(yv.y * fl2);                                                 \
        __syncwarp();                                                                \
        unsigned dse = sh_e[w][PBUF][0];                                             \
        int d = (int)((dse >> 7) & 0xFFu) - 127;                                     \
        /* dot: 8 chains x 8 HFMA2; ee pairs loaded as uint4 (LDS.128) */            \
        unsigned A0 = 0, A1 = 0, A2 = 0, A3 = 0;                                     \
        unsigned B0 = 0, B1 = 0, B2 = 0, B3 = 0;                                     \
        const uint4* ep = (const uint4*)sh_e[w][PBUF];                               \
        _Pragma("unroll")                                                            \
        for (int k = 0; k < 8; ++k) {                                                \
            uint4 ee = ep[k];                                                        \
            if (k & 1) {                                                             \
                A2 = hfma2(ee.x, Eca[4 * k], A2); A3 = hfma2(ee.y, Eca[4 * k + 1], A3); \
                A2 = hfma2(ee.z, Eca[4 * k + 2], A2); A3 = hfma2(ee.w, Eca[4 * k + 3], A3); \
                B2 = hfma2(ee.x, Ecb[4 * k], B2); B3 = hfma2(ee.y, Ecb[4 * k + 1], B3); \
                B2 = hfma2(ee.z, Ecb[4 * k + 2], B2); B3 = hfma2(ee.w, Ecb[4 * k + 3], B3); \
            } else {                                                                 \
                A0 = hfma2(ee.x, Eca[4 * k], A0); A1 = hfma2(ee.y, Eca[4 * k + 1], A1); \
                A0 = hfma2(ee.z, Eca[4 * k + 2], A0); A1 = hfma2(ee.w, Eca[4 * k + 3], A1); \
                B0 = hfma2(ee.x, Ecb[4 * k], B0); B1 = hfma2(ee.y, Ecb[4 * k + 1], B1); \
                B0 = hfma2(ee.z, Ecb[4 * k + 2], B0); B1 = hfma2(ee.w, Ecb[4 * k + 3], B1); \
            }                                                                        \
        }                                                                            \
        unsigned At = hadd2(hadd2(A0, A1), hadd2(A2, A3));                           \
        unsigned Bt = hadd2(hadd2(B0, B1), hadd2(B2, B3));                           \
        float sA = bflo(At) + bfhi(At);                                              \
        float sB = bflo(Bt) + bfhi(Bt);                                              \
        unsigned pk = cvt_bf2(sB * pb, sA * pa);                                     \
        unsigned dd2 = (unsigned)(d * 0x00800080);                                   \
        e = (mcur ? pk : e) - dd2;                                                   \
        C2i += d;                                                                    \
        point += ((sa == yt_cur) ? yv.x * fmcur : 0.0f)                              \
               + ((sb == yt_cur) ? yv.y * fmcur : 0.0f);                             \
        tv += trv_cur * (fmprev * fmcur);                                            \
        sh_e[w][BUF][lane] = e;                                                      \
        fmprev = fmcur;                                                              \
        mcur = mnext; fmcur = mnext ? 1.0f : 0.0f;                                   \
        trv_cur = trv_next; yt_cur = yt_nx; yt_nx = yt_nx2;                          \
    }

    // ---- main loop: t0 === 1 (mod 4); overflow steps run masked (harmless) ----
    for (int t0 = 1; t0 < N; t0 += 4) {
        STEP(t0 + 0, 1, 2, 1, 0)
        STEP(t0 + 1, 2, 3, 0, 1)
        STEP(t0 + 2, 3, 0, 1, 0)
        STEP(t0 + 3, 0, 1, 0, 1)
    }
#undef STEP

    // ---- epilogue: se = sum_j 2^(w_j); alpha2 = C2i + lg2(se) ----
    float se = bflo(e) + bfhi(e);
    float pp = point;
#pragma unroll
    for (int o = 16; o > 0; o >>= 1) {
        se += __shfl_xor_sync(FULL, se, o);
        pp += __shfl_xor_sync(FULL, pp, o);
    }
    if (lane == 0) out[row] = LN2 * ((float)C2i + lg2f(se)) - (pp + tv);
}

extern "C" void kernel_launch(void* const* d_in, const int* in_sizes, int n_in,
                              void* d_out, int out_size) {
    const float* y_pred = (const float*)d_in[0];   // [B, N, K] f32
    const float* trans  = (const float*)d_in[1];   // [K, K]    f32
    const int*   y_true = (const int*)  d_in[2];   // [B, N]    i32
    float* out = (float*)d_out;                    // [B]       f32

    int B = out_size;                  // 512
    int N = in_sizes[2] / B;           // 1024
    int blocks = (B + WPC - 1) / WPC;  // 128
    crf_fwd_kernel<<<blocks, 32 * WPC>>>(y_pred, trans, y_true, out, N, B);
}

// round 17
// speedup vs baseline: 2.9530x; 1.0514x over previous
#include <cuda_runtime.h>
#include <cuda_bf16.h>

#define KDIM  64
#define LOG2E 1.4426950408889634f
#define LN2   0.6931471805599453f
#define WPC   4          // warps (rows) per CTA
#define DIST  4          // emit prefetch distance (steps), power of 2
#define TH    -1000000.0f
#define FULL  0xffffffffu

__device__ __forceinline__ float ex2f(float x){float y;asm("ex2.approx.f32 %0,%1;":"=f"(y):"f"(x));return y;}
__device__ __forceinline__ float lg2f(float x){float y;asm("lg2.approx.f32 %0,%1;":"=f"(y):"f"(x));return y;}
__device__ __forceinline__ unsigned cvt_bf2(float hi, float lo){
    unsigned r;asm("cvt.rn.satfinite.bf16x2.f32 %0,%1,%2;":"=r"(r):"f"(hi),"f"(lo));return r;}
__device__ __forceinline__ float bflo(unsigned u){ return __int_as_float(u << 16); }
__device__ __forceinline__ float bfhi(unsigned u){ return __int_as_float(u & 0xFFFF0000u); }
__device__ __forceinline__ unsigned hfma2(unsigned a, unsigned b, unsigned c){
    unsigned d; asm("fma.rn.bf16x2 %0,%1,%2,%3;":"=r"(d):"r"(a),"r"(b),"r"(c)); return d;}
__device__ __forceinline__ unsigned hadd2(unsigned a, unsigned b){
    unsigned d; asm("add.rn.bf16x2 %0,%1,%2;":"=r"(d):"r"(a),"r"(b)); return d;}

// ONE WARP per batch row; lane l owns states (2l, 2l+1) packed bf16x2.
// Dot s = e x E in bf16 HFMA2 (true dual-MAC). This round (vs R16):
//  - point/tv fully UNIFORM scalar pipelines (R13-verified): no per-lane compares
//  - renorm d from a PRE-SYNC shfl of register e (no post-sync LDS dependency)
//  - STS immediately after e update; bookkeeping after (overlaps sync window)
// Renorm exact: packed bf16x2 exponent subtract (d * 0x00800080), C2i += d int.
// Steps t >= N run masked (m=0): pure frame shift, result invariant.
__global__ __launch_bounds__(32 * WPC, 1) void crf_fwd_kernel(
    const float* __restrict__ y_pred,   // [B, N, K]
    const float* __restrict__ trans,    // [K, K]
    const int*   __restrict__ y_true,   // [B, N]
    float*       __restrict__ out,      // [B]
    int N, int B)
{
    __shared__ __align__(16) unsigned sh_e[WPC][2][32];  // [warp][buf][pair k]

    const int lane = threadIdx.x & 31;
    const int w    = threadIdx.x >> 5;
    const int row  = blockIdx.x * WPC + w;
    if (row >= B) return;

    const int sa = 2 * lane, sb = sa + 1;

    // E columns in bf16x2: Eca[k] = (lo=E[2k][sa], hi=E[2k+1][sa]); Ecb for sb.
    unsigned Eca[32], Ecb[32];
#pragma unroll
    for (int k = 0; k < 32; ++k) {
        Eca[k] = cvt_bf2(__expf(trans[(2 * k + 1) * KDIM + sa]),
                         __expf(trans[(2 * k) * KDIM + sa]));
        Ecb[k] = cvt_bf2(__expf(trans[(2 * k + 1) * KDIM + sb]),
                         __expf(trans[(2 * k) * KDIM + sb]));
    }

    const float* yrow = y_pred + (size_t)row * N * KDIM;
    const int*   trow = y_true + (size_t)row * N;

    // ---- t = 0 ----
    float2 y0 = *(const float2*)(yrow + sa);
    int yt0 = trow[0];
    unsigned m0 = __all_sync(FULL, (y0.x > TH) && (y0.y > TH));
    float fm0 = m0 ? 1.0f : 0.0f;
    unsigned e = cvt_bf2(ex2f((y0.y * fm0) * LOG2E), ex2f((y0.x * fm0) * LOG2E));
    int   C2i = 0;
    float tv = 0.0f;
    sh_e[w][0][lane] = e;
    int d = __shfl_sync(FULL, (int)((e >> 7) & 0xFFu), 0) - 127;   // d for step 1
    float point = yrow[yt0] * fm0;     // uniform
    float fmprev = fm0;

    // ---- prime pipelines ----
    float2 ring[DIST];
#pragma unroll
    for (int p = 1; p <= DIST; ++p) {
        int tt = (p < N) ? p : (N - 1);
        ring[p & (DIST - 1)] = *(const float2*)(yrow + (size_t)tt * KDIM + sa);
    }
    unsigned mcur = __all_sync(FULL, (ring[1 & (DIST - 1)].x > TH) &&
                                     (ring[1 & (DIST - 1)].y > TH));
    if (1 >= N) mcur = 0u;
    float fmcur = mcur ? 1.0f : 0.0f;
    // label pipeline at loop entry T = 1 (R13-verified indices):
    int ytA = trow[(1 < N) ? 1 : (N - 1)];   // yt(T)
    int ytB = trow[(2 < N) ? 2 : (N - 1)];   // yt(T+1)
    int ytC = trow[(3 < N) ? 3 : (N - 1)];   // yt(T+2)
    int ytD = trow[(4 < N) ? 4 : (N - 1)];   // yt(T+3)
    float pgc = yrow[(size_t)((1 < N) ? 1 : (N - 1)) * KDIM + ytA];   // Y[T][yt(T)]
    float pgn = yrow[(size_t)((2 < N) ? 2 : (N - 1)) * KDIM + ytB];   // Y[T+1][yt(T+1)]
    float trvc = trans[yt0 * KDIM + ytA];
    float trvn = trans[ytA * KDIM + ytB];

#define STEP(T, RP, RPN, BUF, PBUF)                                                  \
    {                                                                                \
        /* ------- pre-sync region (independent of e(t-1) exchange) ------- */      \
        float2 yv = ring[RP];                                                        \
        int tt = ((T) + DIST < N) ? ((T) + DIST) : (N - 1);                          \
        ring[RP] = *(const float2*)(yrow + (size_t)tt * KDIM + sa);                  \
        unsigned mnext = __all_sync(FULL, (ring[RPN].x > TH) && (ring[RPN].y > TH)); \
        mnext = ((T) + 1 < N) ? mnext : 0u;                                          \
        int ytL = trow[tt];                                                          \
        float pgN = yrow[(size_t)(((T) + 2 < N) ? ((T) + 2) : (N - 1)) * KDIM + ytC];\
        float trN = trans[ytB * KDIM + ytC];                                         \
        float fl2 = fmcur * LOG2E;                                                   \
        float pa = ex2f(yv.x * fl2);                                                 \
        float pb = ex2f(yv.y * fl2);                                                 \
        unsigned dd2 = (unsigned)(d * 0x00800080);                                   \
        __syncwarp();                                                                \
        /* ------- dot: 8 chains x 8 HFMA2 over broadcast LDS.128 ------- */        \
        unsigned A0 = 0, A1 = 0, A2 = 0, A3 = 0;                                     \
        unsigned B0 = 0, B1 = 0, B2 = 0, B3 = 0;                                     \
        const uint4* ep = (const uint4*)sh_e[w][PBUF];                               \
        _Pragma("unroll")                                                            \
        for (int k = 0; k < 8; ++k) {                                                \
            uint4 ee = ep[k];                                                        \
            if (k & 1) {                                                             \
                A2 = hfma2(ee.x, Eca[4 * k], A2); A3 = hfma2(ee.y, Eca[4 * k + 1], A3); \
                A2 = hfma2(ee.z, Eca[4 * k + 2], A2); A3 = hfma2(ee.w, Eca[4 * k + 3], A3); \
                B2 = hfma2(ee.x, Ecb[4 * k], B2); B3 = hfma2(ee.y, Ecb[4 * k + 1], B3); \
                B2 = hfma2(ee.z, Ecb[4 * k + 2], B2); B3 = hfma2(ee.w, Ecb[4 * k + 3], B3); \
            } else {                                                                 \
                A0 = hfma2(ee.x, Eca[4 * k], A0); A1 = hfma2(ee.y, Eca[4 * k + 1], A1); \
                A0 = hfma2(ee.z, Eca[4 * k + 2], A0); A1 = hfma2(ee.w, Eca[4 * k + 3], A1); \
                B0 = hfma2(ee.x, Ecb[4 * k], B0); B1 = hfma2(ee.y, Ecb[4 * k + 1], B1); \
                B0 = hfma2(ee.z, Ecb[4 * k + 2], B0); B1 = hfma2(ee.w, Ecb[4 * k + 3], B1); \
            }                                                                        \
        }                                                                            \
        unsigned At = hadd2(hadd2(A0, A1), hadd2(A2, A3));                           \
        unsigned Bt = hadd2(hadd2(B0, B1), hadd2(B2, B3));                           \
        float sA = bflo(At) + bfhi(At);                                              \
        float sB = bflo(Bt) + bfhi(Bt);                                              \
        unsigned pk = cvt_bf2(sB * pb, sA * pa);                                     \
        e = (mcur ? pk : e) - dd2;                                                   \
        sh_e[w][BUF][lane] = e;               /* STS asap: releases next sync */     \
        C2i += d;                                                                    \
        d = __shfl_sync(FULL, (int)((e >> 7) & 0xFFu), 0) - 127;  /* for T+1 */      \
        /* ------- uniform bookkeeping (overlaps store/sync window) ------- */      \
        float fmc = fmcur;                                                           \
        point += pgc * fmc;                                                          \
        tv += trvc * (fmprev * fmc);                                                 \
        fmprev = fmc;                                                                \
        mcur = mnext; fmcur = mnext ? 1.0f : 0.0f;                                   \
        pgc = pgn; pgn = pgN;                                                        \
        trvc = trvn; trvn = trN;                                                     \
        ytA = ytB; ytB = ytC; ytC = ytD; ytD = ytL;                                  \
    }

    // ---- main loop: t0 === 1 (mod 4); overflow steps run masked (harmless) ----
    for (int t0 = 1; t0 < N; t0 += 4) {
        STEP(t0 + 0, 1, 2, 1, 0)
        STEP(t0 + 1, 2, 3, 0, 1)
        STEP(t0 + 2, 3, 0, 1, 0)
        STEP(t0 + 3, 0, 1, 0, 1)
    }
#undef STEP

    // ---- epilogue: se = sum_j 2^(w_j); point/tv are uniform ----
    float se = bflo(e) + bfhi(e);
#pragma unroll
    for (int o = 16; o > 0; o >>= 1)
        se += __shfl_xor_sync(FULL, se, o);
    if (lane == 0) out[row] = LN2 * ((float)C2i + lg2f(se)) - (point + tv);
}

extern "C" void kernel_launch(void* const* d_in, const int* in_sizes, int n_in,
                              void* d_out, int out_size) {
    const float* y_pred = (const float*)d_in[0];   // [B, N, K] f32
    const float* trans  = (const float*)d_in[1];   // [K, K]    f32
    const int*   y_true = (const int*)  d_in[2];   // [B, N]    i32
    float* out = (float*)d_out;                    // [B]       f32

    int B = out_size;                  // 512
    int N = in_sizes[2] / B;           // 1024
    int blocks = (B + WPC - 1) / WPC;  // 128
    crf_fwd_kernel<<<blocks, 32 * WPC>>>(y_pred, trans, y_true, out, N, B);
}